// round 13
// baseline (speedup 1.0000x reference)
#include <cuda_runtime.h>
#include <cuda_bf16.h>

// Problem geometry (fixed by the dataset).
static constexpr int Dv = 160;
static constexpr int Hv = 192;
static constexpr int Wv = 160;
static constexpr int SH = Wv;           // stride of one h-row
static constexpr int SD = Hv * Wv;      // stride of one d-slice (30720)
static constexpr int V  = Dv * Hv * Wv; // 4,915,200 voxels
static constexpr int QUAR = V / 4;      // threads (4 consecutive-x voxels each)

// Affine fold constants (double-evaluated, rounded to fp32).
// Stage B:  j = (coord + of*rf) * (S/(S-1)) - 0.5
static constexpr float CW = (float)(160.0 / 159.0);
static constexpr float CH = (float)(192.0 / 191.0);
static constexpr float CD = (float)(160.0 / 159.0);
// Stage A:  i = ((g+1)*S - 1) * 0.5 = g*(S/2) + (S-1)/2
static constexpr float AW = 80.0f,  BW = 79.5f;
static constexpr float AH = 96.0f,  BH = 95.5f;
static constexpr float AD = 80.0f,  BD = 79.5f;

// ---------------------------------------------------------------------------
// Trilinear sample of src, zeros padding; interior fast path with one base
// pointer + 8 constant-offset loads, sequential consume (R10 showed explicit
// cross-voxel batching buys nothing).
// ---------------------------------------------------------------------------
__device__ __noinline__ float samp_src_slow(const float* __restrict__ v,
                                            float ix, float iy, float iz) {
    float xf = floorf(ix), yf = floorf(iy), zf = floorf(iz);
    float tx = ix - xf,    ty = iy - yf,    tz = iz - zf;
    int   x0 = (int)xf,    y0 = (int)yf,    z0 = (int)zf;

    float wx0 = 1.0f - tx, wy0 = 1.0f - ty, wz0 = 1.0f - tz;
    float a = wz0 * wy0, b = wz0 * ty, c = tz * wy0, e = tz * ty;

    bool bx0 = (unsigned)x0       < (unsigned)Wv;
    bool bx1 = (unsigned)(x0 + 1) < (unsigned)Wv;
    bool by0 = (unsigned)y0       < (unsigned)Hv;
    bool by1 = (unsigned)(y0 + 1) < (unsigned)Hv;
    bool bz0 = (unsigned)z0       < (unsigned)Dv;
    bool bz1 = (unsigned)(z0 + 1) < (unsigned)Dv;

    int cx0 = min(max(x0,     0), Wv - 1), cx1 = min(max(x0 + 1, 0), Wv - 1);
    int cy0 = min(max(y0,     0), Hv - 1), cy1 = min(max(y0 + 1, 0), Hv - 1);
    int cz0 = min(max(z0,     0), Dv - 1), cz1 = min(max(z0 + 1, 0), Dv - 1);

    float acc = 0.0f;
    acc += v[(cz0 * Hv + cy0) * Wv + cx0] * ((a * wx0) * ((bz0 & by0 & bx0) ? 1.0f : 0.0f));
    acc += v[(cz0 * Hv + cy0) * Wv + cx1] * ((a * tx ) * ((bz0 & by0 & bx1) ? 1.0f : 0.0f));
    acc += v[(cz0 * Hv + cy1) * Wv + cx0] * ((b * wx0) * ((bz0 & by1 & bx0) ? 1.0f : 0.0f));
    acc += v[(cz0 * Hv + cy1) * Wv + cx1] * ((b * tx ) * ((bz0 & by1 & bx1) ? 1.0f : 0.0f));
    acc += v[(cz1 * Hv + cy0) * Wv + cx0] * ((c * wx0) * ((bz1 & by0 & bx0) ? 1.0f : 0.0f));
    acc += v[(cz1 * Hv + cy0) * Wv + cx1] * ((c * tx ) * ((bz1 & by0 & bx1) ? 1.0f : 0.0f));
    acc += v[(cz1 * Hv + cy1) * Wv + cx0] * ((e * wx0) * ((bz1 & by1 & bx0) ? 1.0f : 0.0f));
    acc += v[(cz1 * Hv + cy1) * Wv + cx1] * ((e * tx ) * ((bz1 & by1 & bx1) ? 1.0f : 0.0f));
    return acc;
}

__device__ __forceinline__ float samp_src(const float* __restrict__ v,
                                          float ix, float iy, float iz) {
    float xf = floorf(ix), yf = floorf(iy), zf = floorf(iz);
    float tx = ix - xf,    ty = iy - yf,    tz = iz - zf;
    int   x0 = (int)xf,    y0 = (int)yf,    z0 = (int)zf;

    float wx0 = 1.0f - tx, wy0 = 1.0f - ty, wz0 = 1.0f - tz;
    float a = wz0 * wy0;   // z0,y0
    float b = wz0 * ty;    // z0,y1
    float c = tz  * wy0;   // z1,y0
    float e = tz  * ty;    // z1,y1

    bool in = ((unsigned)x0       < (unsigned)Wv) &
              ((unsigned)(x0 + 1) < (unsigned)Wv) &
              ((unsigned)y0       < (unsigned)Hv) &
              ((unsigned)(y0 + 1) < (unsigned)Hv) &
              ((unsigned)z0       < (unsigned)Dv) &
              ((unsigned)(z0 + 1) < (unsigned)Dv);

    if (in) {
        const float* p = v + ((z0 * Hv + y0) * Wv + x0);
        float acc;
        acc  = p[0]           * (a * wx0);
        acc += p[1]           * (a * tx );
        acc += p[SH]          * (b * wx0);
        acc += p[SH + 1]      * (b * tx );
        acc += p[SD]          * (c * wx0);
        acc += p[SD + 1]      * (c * tx );
        acc += p[SD + SH]     * (e * wx0);
        acc += p[SD + SH + 1] * (e * tx );
        return acc;
    }
    return samp_src_slow(v, ix, iy, iz);
}

// ---------------------------------------------------------------------------
// Trilinear sample of the 3-channel flow1 volume, zeros padding. The
// reference feeds RAW voxel coordinates through the [-1,1] unnormalizer, so
// this is fully out of bounds for essentially every voxel. Caller does the
// cheap fully-out test; this is the rare slow path (out of line so its
// registers don't bloat the hot path).
// ---------------------------------------------------------------------------
__device__ __noinline__ void samp_flow(const float* __restrict__ f,
                                       float ix, float iy, float iz,
                                       float& o0, float& o1, float& o2) {
    float xf = floorf(ix), yf = floorf(iy), zf = floorf(iz);
    int   x0 = (int)xf,    y0 = (int)yf,    z0 = (int)zf;

    float tx = ix - xf, ty = iy - yf, tz = iz - zf;
    float wx0 = 1.0f - tx, wy0 = 1.0f - ty, wz0 = 1.0f - tz;
    float a = wz0 * wy0, b = wz0 * ty, c = tz * wy0, e = tz * ty;

    bool bx0 = (unsigned)x0       < (unsigned)Wv;
    bool bx1 = (unsigned)(x0 + 1) < (unsigned)Wv;
    bool by0 = (unsigned)y0       < (unsigned)Hv;
    bool by1 = (unsigned)(y0 + 1) < (unsigned)Hv;
    bool bz0 = (unsigned)z0       < (unsigned)Dv;
    bool bz1 = (unsigned)(z0 + 1) < (unsigned)Dv;

    int cx0 = min(max(x0,     0), Wv - 1), cx1 = min(max(x0 + 1, 0), Wv - 1);
    int cy0 = min(max(y0,     0), Hv - 1), cy1 = min(max(y0 + 1, 0), Hv - 1);
    int cz0 = min(max(z0,     0), Dv - 1), cz1 = min(max(z0 + 1, 0), Dv - 1);

    int   idx[8];
    float wgt[8];
    idx[0] = (cz0 * Hv + cy0) * Wv + cx0; wgt[0] = (a * wx0) * ((bz0 & by0 & bx0) ? 1.0f : 0.0f);
    idx[1] = (cz0 * Hv + cy0) * Wv + cx1; wgt[1] = (a * tx ) * ((bz0 & by0 & bx1) ? 1.0f : 0.0f);
    idx[2] = (cz0 * Hv + cy1) * Wv + cx0; wgt[2] = (b * wx0) * ((bz0 & by1 & bx0) ? 1.0f : 0.0f);
    idx[3] = (cz0 * Hv + cy1) * Wv + cx1; wgt[3] = (b * tx ) * ((bz0 & by1 & bx1) ? 1.0f : 0.0f);
    idx[4] = (cz1 * Hv + cy0) * Wv + cx0; wgt[4] = (c * wx0) * ((bz1 & by0 & bx0) ? 1.0f : 0.0f);
    idx[5] = (cz1 * Hv + cy0) * Wv + cx1; wgt[5] = (c * tx ) * ((bz1 & by0 & bx1) ? 1.0f : 0.0f);
    idx[6] = (cz1 * Hv + cy1) * Wv + cx0; wgt[6] = (e * wx0) * ((bz1 & by1 & bx0) ? 1.0f : 0.0f);
    idx[7] = (cz1 * Hv + cy1) * Wv + cx1; wgt[7] = (e * tx ) * ((bz1 & by1 & bx1) ? 1.0f : 0.0f);

    float s0 = 0.f, s1 = 0.f, s2 = 0.f;
#pragma unroll
    for (int k = 0; k < 8; k++) {
        float wk = wgt[k];
        int   ik = idx[k];
        s0 += f[ik]         * wk;
        s1 += f[V + ik]     * wk;
        s2 += f[2 * V + ik] * wk;
    }
    o0 = s0; o1 = s1; o2 = s2;
}

// ---------------------------------------------------------------------------
// Fused kernel: 4 consecutive-x voxels per thread (p = 4t .. 4t+3).
// W = 160 divisible by 4 -> quad never crosses a row; V divisible by 4 ->
// every plane is 16B-aligned for float4 loads/stores.
// Mem instrs/voxel: 8 gathers + 0.75 LDG.128 + 1 STG.128 = 9.75 (was 11.5).
//   out[0 : V ) = deform_2_img
//   out[V : 2V) = out_flow ch0 (d)
//   out[2V: 3V) = out_flow ch1 (h)
//   out[3V: 4V) = out_flow ch2 (w)
// ---------------------------------------------------------------------------
__global__ void __launch_bounds__(256, 4)
spatial_transformer_quad(const float* __restrict__ src,
                         const float* __restrict__ flow1,
                         const float* __restrict__ flow2,
                         const float* __restrict__ rf_ptr,
                         float* __restrict__ out) {
    int t = blockIdx.x * blockDim.x + threadIdx.x;   // 0 .. QUAR-1
    const float rf = __ldg(rf_ptr);

    const int p = 4 * t;              // 16B-aligned voxel index
    int w = p % Wv;                   // multiple of 4, quad stays in-row
    int r = p / Wv;
    int h = r % Hv;
    int d = r / Hv;

    const float fw_ = (float)w;
    const float fh_ = (float)h;
    const float fd_ = (float)d;

    // Vectorized flow2 loads (16B-aligned).
    float4 F2d = *reinterpret_cast<const float4*>(flow2 + p);
    float4 F2h = *reinterpret_cast<const float4*>(flow2 + V + p);
    float4 F2w = *reinterpret_cast<const float4*>(flow2 + 2 * V + p);

    const float f2d[4] = {F2d.x, F2d.y, F2d.z, F2d.w};
    const float f2h[4] = {F2h.x, F2h.y, F2h.z, F2h.w};
    const float f2w[4] = {F2w.x, F2w.y, F2w.z, F2w.w};

    // ---- Stage A (all 4 voxels): raw voxel coords through the [-1,1]
    // unnormalizer (bug-compatible): i = g*S/2 + (S-1)/2. Almost always
    // fully out of bounds -> zero contribution.
    float ofd[4], ofh[4], ofw[4];
#pragma unroll
    for (int k = 0; k < 4; k++) {
        float gz = fmaf(f2d[k], rf, fd_);
        float gy = fmaf(f2h[k], rf, fh_);
        float gx = fmaf(f2w[k], rf, fw_ + (float)k);

        float ix = fmaf(gx, AW, BW);
        float iy = fmaf(gy, AH, BH);
        float iz = fmaf(gz, AD, BD);

        float a0 = 0.f, a1 = 0.f, a2 = 0.f;
        if (!(ix < -1.0f || ix >= (float)Wv ||
              iy < -1.0f || iy >= (float)Hv ||
              iz < -1.0f || iz >= (float)Dv))
            samp_flow(flow1, ix, iy, iz, a0, a1, a2);

        ofd[k] = a0 + f2d[k];
        ofh[k] = a1 + f2h[k];
        ofw[k] = a2 + f2w[k];
    }

    // Retire out_flow stores before the gather phase (frees live registers).
    *reinterpret_cast<float4*>(out + V + p)     = make_float4(ofd[0], ofd[1], ofd[2], ofd[3]);
    *reinterpret_cast<float4*>(out + 2 * V + p) = make_float4(ofh[0], ofh[1], ofh[2], ofh[3]);
    *reinterpret_cast<float4*>(out + 3 * V + p) = make_float4(ofw[0], ofw[1], ofw[2], ofw[3]);

    // ---- Stage B: folded affine  j = (coord + of*rf) * S/(S-1) - 0.5,
    // then trilinear gather of src. Sequential per voxel (low live-register
    // pressure); compiler interleaves across the unrolled iterations.
    float img[4];
#pragma unroll
    for (int k = 0; k < 4; k++) {
        float jz = fmaf(fmaf(ofd[k], rf, fd_), CD, -0.5f);
        float jy = fmaf(fmaf(ofh[k], rf, fh_), CH, -0.5f);
        float jx = fmaf(fmaf(ofw[k], rf, fw_ + (float)k), CW, -0.5f);
        img[k] = samp_src(src, jx, jy, jz);
    }

    *reinterpret_cast<float4*>(out + p) = make_float4(img[0], img[1], img[2], img[3]);
}

extern "C" void kernel_launch(void* const* d_in, const int* in_sizes, int n_in,
                              void* d_out, int out_size) {
    // metadata order: src, flow1, flow2, grid (unused: analytic meshgrid),
    // range_flow (device scalar).
    const float* src   = (const float*)d_in[0];
    const float* flow1 = (const float*)d_in[1];
    const float* flow2 = (const float*)d_in[2];
    const float* rf    = (const float*)d_in[4];
    float* out = (float*)d_out;

    const int threads = 256;
    const int blocks  = QUAR / threads; // 4800
    spatial_transformer_quad<<<blocks, threads>>>(src, flow1, flow2, rf, out);
}

// round 16
// speedup vs baseline: 1.0204x; 1.0204x over previous
#include <cuda_runtime.h>
#include <cuda_bf16.h>

// Problem geometry (fixed by the dataset).
static constexpr int Dv = 160;
static constexpr int Hv = 192;
static constexpr int Wv = 160;
static constexpr int SH = Wv;           // stride of one h-row
static constexpr int SD = Hv * Wv;      // stride of one d-slice (30720)
static constexpr int V  = Dv * Hv * Wv; // 4,915,200 voxels
static constexpr int HALF = V / 2;      // threads (2 consecutive-x voxels each)

// Affine fold constants (double-evaluated, rounded to fp32).
// Stage B:  j = (coord + of*rf) * (S/(S-1)) - 0.5
static constexpr float CW = (float)(160.0 / 159.0);
static constexpr float CH = (float)(192.0 / 191.0);
static constexpr float CD = (float)(160.0 / 159.0);
// Stage A:  i = ((g+1)*S - 1) * 0.5 = g*(S/2) + (S-1)/2
static constexpr float AW = 80.0f,  BW = 79.5f;
static constexpr float AH = 96.0f,  BH = 95.5f;
static constexpr float AD = 80.0f,  BD = 79.5f;

// ---------------------------------------------------------------------------
// Trilinear sample of the single-channel src volume, zeros padding.
// Interior fast path: one base pointer + 8 constant-offset loads.
// ---------------------------------------------------------------------------
__device__ __forceinline__ float samp_src(const float* __restrict__ v,
                                          float ix, float iy, float iz) {
    float xf = floorf(ix), yf = floorf(iy), zf = floorf(iz);
    float tx = ix - xf,    ty = iy - yf,    tz = iz - zf;
    int   x0 = (int)xf,    y0 = (int)yf,    z0 = (int)zf;

    float wx0 = 1.0f - tx, wy0 = 1.0f - ty, wz0 = 1.0f - tz;
    float a = wz0 * wy0;   // z0,y0
    float b = wz0 * ty;    // z0,y1
    float c = tz  * wy0;   // z1,y0
    float e = tz  * ty;    // z1,y1

    bool bx0 = (unsigned)x0       < (unsigned)Wv;
    bool bx1 = (unsigned)(x0 + 1) < (unsigned)Wv;
    bool by0 = (unsigned)y0       < (unsigned)Hv;
    bool by1 = (unsigned)(y0 + 1) < (unsigned)Hv;
    bool bz0 = (unsigned)z0       < (unsigned)Dv;
    bool bz1 = (unsigned)(z0 + 1) < (unsigned)Dv;

    if (bx0 & bx1 & by0 & by1 & bz0 & bz1) {
        const float* p = v + ((z0 * Hv + y0) * Wv + x0);
        float acc;
        acc  = p[0]           * (a * wx0);
        acc += p[1]           * (a * tx );
        acc += p[SH]          * (b * wx0);
        acc += p[SH + 1]      * (b * tx );
        acc += p[SD]          * (c * wx0);
        acc += p[SD + 1]      * (c * tx );
        acc += p[SD + SH]     * (e * wx0);
        acc += p[SD + SH + 1] * (e * tx );
        return acc;
    }

    // Boundary path: clamp indices + zero-mask weights (reference-equivalent).
    int cx0 = min(max(x0,     0), Wv - 1), cx1 = min(max(x0 + 1, 0), Wv - 1);
    int cy0 = min(max(y0,     0), Hv - 1), cy1 = min(max(y0 + 1, 0), Hv - 1);
    int cz0 = min(max(z0,     0), Dv - 1), cz1 = min(max(z0 + 1, 0), Dv - 1);

    float acc = 0.0f;
    acc += v[(cz0 * Hv + cy0) * Wv + cx0] * ((a * wx0) * ((bz0 & by0 & bx0) ? 1.0f : 0.0f));
    acc += v[(cz0 * Hv + cy0) * Wv + cx1] * ((a * tx ) * ((bz0 & by0 & bx1) ? 1.0f : 0.0f));
    acc += v[(cz0 * Hv + cy1) * Wv + cx0] * ((b * wx0) * ((bz0 & by1 & bx0) ? 1.0f : 0.0f));
    acc += v[(cz0 * Hv + cy1) * Wv + cx1] * ((b * tx ) * ((bz0 & by1 & bx1) ? 1.0f : 0.0f));
    acc += v[(cz1 * Hv + cy0) * Wv + cx0] * ((c * wx0) * ((bz1 & by0 & bx0) ? 1.0f : 0.0f));
    acc += v[(cz1 * Hv + cy0) * Wv + cx1] * ((c * tx ) * ((bz1 & by0 & bx1) ? 1.0f : 0.0f));
    acc += v[(cz1 * Hv + cy1) * Wv + cx0] * ((e * wx0) * ((bz1 & by1 & bx0) ? 1.0f : 0.0f));
    acc += v[(cz1 * Hv + cy1) * Wv + cx1] * ((e * tx ) * ((bz1 & by1 & bx1) ? 1.0f : 0.0f));
    return acc;
}

// ---------------------------------------------------------------------------
// Trilinear sample of the 3-channel flow1 volume, zeros padding. The
// reference feeds RAW voxel coordinates through the [-1,1] unnormalizer, so
// this is fully out of bounds for essentially every voxel. Caller does the
// cheap fully-out test; this is the rare slow path (out of line so its
// registers don't bloat the hot path).
// ---------------------------------------------------------------------------
__device__ __noinline__ void samp_flow(const float* __restrict__ f,
                                       float ix, float iy, float iz,
                                       float& o0, float& o1, float& o2) {
    float xf = floorf(ix), yf = floorf(iy), zf = floorf(iz);
    int   x0 = (int)xf,    y0 = (int)yf,    z0 = (int)zf;

    float tx = ix - xf, ty = iy - yf, tz = iz - zf;
    float wx0 = 1.0f - tx, wy0 = 1.0f - ty, wz0 = 1.0f - tz;
    float a = wz0 * wy0, b = wz0 * ty, c = tz * wy0, e = tz * ty;

    bool bx0 = (unsigned)x0       < (unsigned)Wv;
    bool bx1 = (unsigned)(x0 + 1) < (unsigned)Wv;
    bool by0 = (unsigned)y0       < (unsigned)Hv;
    bool by1 = (unsigned)(y0 + 1) < (unsigned)Hv;
    bool bz0 = (unsigned)z0       < (unsigned)Dv;
    bool bz1 = (unsigned)(z0 + 1) < (unsigned)Dv;

    int cx0 = min(max(x0,     0), Wv - 1), cx1 = min(max(x0 + 1, 0), Wv - 1);
    int cy0 = min(max(y0,     0), Hv - 1), cy1 = min(max(y0 + 1, 0), Hv - 1);
    int cz0 = min(max(z0,     0), Dv - 1), cz1 = min(max(z0 + 1, 0), Dv - 1);

    int   idx[8];
    float wgt[8];
    idx[0] = (cz0 * Hv + cy0) * Wv + cx0; wgt[0] = (a * wx0) * ((bz0 & by0 & bx0) ? 1.0f : 0.0f);
    idx[1] = (cz0 * Hv + cy0) * Wv + cx1; wgt[1] = (a * tx ) * ((bz0 & by0 & bx1) ? 1.0f : 0.0f);
    idx[2] = (cz0 * Hv + cy1) * Wv + cx0; wgt[2] = (b * wx0) * ((bz0 & by1 & bx0) ? 1.0f : 0.0f);
    idx[3] = (cz0 * Hv + cy1) * Wv + cx1; wgt[3] = (b * tx ) * ((bz0 & by1 & bx1) ? 1.0f : 0.0f);
    idx[4] = (cz1 * Hv + cy0) * Wv + cx0; wgt[4] = (c * wx0) * ((bz1 & by0 & bx0) ? 1.0f : 0.0f);
    idx[5] = (cz1 * Hv + cy0) * Wv + cx1; wgt[5] = (c * tx ) * ((bz1 & by0 & bx1) ? 1.0f : 0.0f);
    idx[6] = (cz1 * Hv + cy1) * Wv + cx0; wgt[6] = (e * wx0) * ((bz1 & by1 & bx0) ? 1.0f : 0.0f);
    idx[7] = (cz1 * Hv + cy1) * Wv + cx1; wgt[7] = (e * tx ) * ((bz1 & by1 & bx1) ? 1.0f : 0.0f);

    float s0 = 0.f, s1 = 0.f, s2 = 0.f;
#pragma unroll
    for (int k = 0; k < 8; k++) {
        float wk = wgt[k];
        int   ik = idx[k];
        s0 += f[ik]         * wk;
        s1 += f[V + ik]     * wk;
        s2 += f[2 * V + ik] * wk;
    }
    o0 = s0; o1 = s1; o2 = s2;
}

// ---------------------------------------------------------------------------
// One voxel of the fused pipeline (coordinates -> out_flow + sampled image).
// ---------------------------------------------------------------------------
__device__ __forceinline__ void do_voxel(const float* __restrict__ src,
                                         const float* __restrict__ flow1,
                                         float fw_, float fh_, float fd_,
                                         float f2d, float f2h, float f2w,
                                         float rf,
                                         float& img, float& ofd, float& ofh, float& ofw) {
    // Stage A: grid2 = grid + flow2*rf (raw voxel coords) pushed through the
    // align_corners=False unnormalizer (bug-compatible): i = g*S/2 + (S-1)/2.
    float gz = fmaf(f2d, rf, fd_);
    float gy = fmaf(f2h, rf, fh_);
    float gx = fmaf(f2w, rf, fw_);

    float ix = fmaf(gx, AW, BW);
    float iy = fmaf(gy, AH, BH);
    float iz = fmaf(gz, AD, BD);

    // Fully-out test without floor: floor(i) < -1 <=> i < -1 ; floor(i) >= S
    // <=> i >= S. Zero padding kills all 8 corners.
    float fw0 = 0.f, fw1 = 0.f, fw2 = 0.f;
    if (!(ix < -1.0f || ix >= (float)Wv ||
          iy < -1.0f || iy >= (float)Hv ||
          iz < -1.0f || iz >= (float)Dv)) {
        samp_flow(flow1, ix, iy, iz, fw0, fw1, fw2);
    }

    ofd = fw0 + f2d;
    ofh = fw1 + f2h;
    ofw = fw2 + f2w;

    // Stage B folded affine: j = (coord + of*rf) * S/(S-1) - 0.5
    float jz = fmaf(fmaf(ofd, rf, fd_), CD, -0.5f);
    float jy = fmaf(fmaf(ofh, rf, fh_), CH, -0.5f);
    float jx = fmaf(fmaf(ofw, rf, fw_), CW, -0.5f);

    img = samp_src(src, jx, jy, jz);
}

// ---------------------------------------------------------------------------
// Fused kernel: 2 consecutive-x voxels per thread (p = 2t, 2t+1). W = 160 is
// even, so a pair never crosses a row; V is even, so every channel plane and
// output plane stays 8-byte aligned for float2 loads/stores.
// Mem instrs/voxel: 8 gathers + 1.5 LDG.64 + 2 STG.64 = 11.5.
// __launch_bounds__(256, 6): force regs <= 42 -> 6 blocks/SM (75% theoretical
// occupancy vs 51% measured at 48 regs) to raise concurrent gather demand at
// the L1 (binding pipe, 79.5% at occ 51%).
//   out[0 : V ) = deform_2_img
//   out[V : 2V) = out_flow ch0 (d)
//   out[2V: 3V) = out_flow ch1 (h)
//   out[3V: 4V) = out_flow ch2 (w)
// ---------------------------------------------------------------------------
__global__ void __launch_bounds__(256, 6)
spatial_transformer_pair(const float* __restrict__ src,
                         const float* __restrict__ flow1,
                         const float* __restrict__ flow2,
                         const float* __restrict__ rf_ptr,
                         float* __restrict__ out) {
    int t = blockIdx.x * blockDim.x + threadIdx.x;   // 0 .. HALF-1
    const float rf = __ldg(rf_ptr);

    const int p = 2 * t;              // even voxel index
    int w = p % Wv;                   // even, pair stays in-row
    int r = p / Wv;
    int h = r % Hv;
    int d = r / Hv;

    const float fw_ = (float)w;
    const float fh_ = (float)h;
    const float fd_ = (float)d;

    // Vectorized flow2 loads (8B-aligned: p even, V even).
    float2 F2d = *reinterpret_cast<const float2*>(flow2 + p);
    float2 F2h = *reinterpret_cast<const float2*>(flow2 + V + p);
    float2 F2w = *reinterpret_cast<const float2*>(flow2 + 2 * V + p);

    float img0, ofd0, ofh0, ofw0;
    float img1, ofd1, ofh1, ofw1;

    do_voxel(src, flow1, fw_,        fh_, fd_, F2d.x, F2h.x, F2w.x, rf,
             img0, ofd0, ofh0, ofw0);
    do_voxel(src, flow1, fw_ + 1.0f, fh_, fd_, F2d.y, F2h.y, F2w.y, rf,
             img1, ofd1, ofh1, ofw1);

    // Vectorized stores.
    *reinterpret_cast<float2*>(out + p)         = make_float2(img0, img1);
    *reinterpret_cast<float2*>(out + V + p)     = make_float2(ofd0, ofd1);
    *reinterpret_cast<float2*>(out + 2 * V + p) = make_float2(ofh0, ofh1);
    *reinterpret_cast<float2*>(out + 3 * V + p) = make_float2(ofw0, ofw1);
}

extern "C" void kernel_launch(void* const* d_in, const int* in_sizes, int n_in,
                              void* d_out, int out_size) {
    // metadata order: src, flow1, flow2, grid (unused: analytic meshgrid),
    // range_flow (device scalar).
    const float* src   = (const float*)d_in[0];
    const float* flow1 = (const float*)d_in[1];
    const float* flow2 = (const float*)d_in[2];
    const float* rf    = (const float*)d_in[4];
    float* out = (float*)d_out;

    const int threads = 256;
    const int blocks  = HALF / threads; // 9600
    spatial_transformer_pair<<<blocks, threads>>>(src, flow1, flow2, rf, out);
}